// round 3
// baseline (speedup 1.0000x reference)
#include <cuda_runtime.h>
#include <cuda_bf16.h>
#include <mma.h>
#include <cstdint>

#define NN 50000
#define NE 800000
#define HID 128
#define LATD 64
#define IN_NODE 11
#define IN_EDGE 4

// ---------------- device scratch ----------------
__device__ float g_h0buf[NN * HID];
__device__ float g_h1buf[NN * HID];
__device__ float g_agg[NN * HID];
__device__ float g_P1[NN * HID];
__device__ float g_P2[NN * HID];
__device__ float g_radial[NE];
__device__ float g_wsum[HID * HID];
// W2 per layer as [K=128][N=128] bf16, split hi/lo
__device__ __nv_bfloat16 g_Bh[2][HID * HID];
__device__ __nv_bfloat16 g_Bl[2][HID * HID];

__device__ __forceinline__ float elu(float v) {
    return v > 0.f ? v : (__expf(v) - 1.f);
}

__device__ __forceinline__ void red4(float* p, float a, float b, float c, float d) {
    asm volatile("red.global.add.v4.f32 [%0], {%1,%2,%3,%4};"
                 :: "l"(p), "f"(a), "f"(b), "f"(c), "f"(d) : "memory");
}

__device__ __forceinline__ uint32_t pack_bf16(float e0, float e1) {
    // bits[15:0] = e0 (lower k), bits[31:16] = e1
    uint32_t r;
    asm("cvt.rn.bf16x2.f32 %0, %1, %2;" : "=r"(r) : "f"(e1), "f"(e0));
    return r;
}

// ---------------- small kernels ----------------
__global__ void embed_kernel(const float* __restrict__ h0,
                             const float* __restrict__ emb_w,
                             const float* __restrict__ emb_b) {
    int idx = blockIdx.x * 256 + threadIdx.x;
    if (idx >= NN * HID) return;
    int n = idx >> 7, j = idx & 127;
    float acc = emb_b[j];
#pragma unroll
    for (int k = 0; k < IN_NODE; k++)
        acc += h0[n * IN_NODE + k] * emb_w[k * HID + j];
    g_h0buf[idx] = acc;
}

__global__ void radial_kernel(const float* __restrict__ x,
                              const int* __restrict__ row,
                              const int* __restrict__ col) {
    int e = blockIdx.x * 256 + threadIdx.x;
    if (e >= NE) return;
    int r = row[e], c = col[e];
    float dx = x[r * 3 + 0] - x[c * 3 + 0];
    float dy = x[r * 3 + 1] - x[c * 3 + 1];
    float dz = x[r * 3 + 2] - x[c * 3 + 2];
    g_radial[e] = dx * dx + dy * dy + dz * dz;
}

__global__ void zero_agg_kernel() {
    int i = blockIdx.x * 256 + threadIdx.x;
    if (i < NN * HID) g_agg[i] = 0.f;
}

__global__ void wsum_kernel(const float* __restrict__ nw1, int layer) {
    int i = blockIdx.x * 256 + threadIdx.x;
    if (i >= HID * HID) return;
    int k = i >> 7, j = i & 127;
    const float* base = nw1 + layer * (3 * HID) * HID;
    g_wsum[i] = base[k * HID + j] + base[(2 * HID + k) * HID + j];
}

// split W2 into bf16 hi/lo, layout [K][N] (same as stored)
__global__ void w2prep_kernel(const float* __restrict__ ew2) {
    int idx = blockIdx.x * 256 + threadIdx.x;
    if (idx >= 2 * HID * HID) return;
    int layer = idx >> 14;
    int rem = idx & 16383;
    float v = ew2[layer * HID * HID + rem];
    __nv_bfloat16 hb = __float2bfloat16(v);
    float lres = v - __bfloat162float(hb);
    g_Bh[layer][rem] = hb;
    g_Bl[layer][rem] = __float2bfloat16(lres);
}

// ---------------- P1/P2 precompute (fp32 SIMT) ----------------
__global__ void __launch_bounds__(256, 2)
pre_kernel(const float* __restrict__ ew1, int layer) {
    __shared__ float As[32 * 132];
    __shared__ float Bs[32 * 132];
    const float* src = (layer == 0) ? g_h0buf : g_h1buf;
    const float* W = ew1 + (layer * 261 + blockIdx.y * HID) * HID;
    float* P = blockIdx.y ? g_P2 : g_P1;

    int tid = threadIdx.x;
    int tx = tid & 15, ty = tid >> 4;
    int n0 = blockIdx.x * 128;

    float acc[8][8];
#pragma unroll
    for (int i = 0; i < 8; i++)
#pragma unroll
        for (int j = 0; j < 8; j++) acc[i][j] = 0.f;

    for (int k0 = 0; k0 < HID; k0 += 32) {
#pragma unroll
        for (int it = 0; it < 4; it++) {
            int s = tid + it * 256;
            int e = s >> 3, kq = s & 7;
            int n = n0 + e;
            float4 v = make_float4(0.f, 0.f, 0.f, 0.f);
            if (n < NN) v = *(const float4*)(src + n * HID + k0 + kq * 4);
            As[(kq * 4 + 0) * 132 + e] = v.x;
            As[(kq * 4 + 1) * 132 + e] = v.y;
            As[(kq * 4 + 2) * 132 + e] = v.z;
            As[(kq * 4 + 3) * 132 + e] = v.w;
        }
#pragma unroll
        for (int it = 0; it < 4; it++) {
            int s = tid + it * 256;
            int kk = s >> 5, jq = s & 31;
            *(float4*)(Bs + kk * 132 + jq * 4) =
                *(const float4*)(W + (k0 + kk) * HID + jq * 4);
        }
        __syncthreads();
#pragma unroll
        for (int kk = 0; kk < 32; kk++) {
            float4 a0 = *(const float4*)(As + kk * 132 + ty * 8);
            float4 a1 = *(const float4*)(As + kk * 132 + ty * 8 + 4);
            float4 b0 = *(const float4*)(Bs + kk * 132 + tx * 8);
            float4 b1 = *(const float4*)(Bs + kk * 132 + tx * 8 + 4);
            float a[8] = {a0.x, a0.y, a0.z, a0.w, a1.x, a1.y, a1.z, a1.w};
            float b[8] = {b0.x, b0.y, b0.z, b0.w, b1.x, b1.y, b1.z, b1.w};
#pragma unroll
            for (int i = 0; i < 8; i++)
#pragma unroll
                for (int j = 0; j < 8; j++) acc[i][j] += a[i] * b[j];
        }
        __syncthreads();
    }
#pragma unroll
    for (int i = 0; i < 8; i++) {
        int n = n0 + ty * 8 + i;
        if (n < NN) {
#pragma unroll
            for (int j = 0; j < 8; j += 4) {
                float4 v = make_float4(acc[i][j], acc[i][j + 1], acc[i][j + 2], acc[i][j + 3]);
                *(float4*)(P + n * HID + tx * 8 + j) = v;
            }
        }
    }
}

// ---------------- edge kernel: gather+ELU -> SMEM bf16 hi/lo, wmma 3-pass, scatter ----------------
// SMEM layout (bytes):
static constexpr int AST = 136;  // bf16 row stride for A/B tiles
static constexpr int DST = 132;  // f32 row stride for D
static constexpr int SM_AHI = 0;                        // 128*136*2 = 34816
static constexpr int SM_ALO = 34816;
static constexpr int SM_BHI = 69632;
static constexpr int SM_BLO = 104448;
static constexpr int SM_D   = 139264;                   // 128*132*4 = 67584
static constexpr int SM_WT  = 206848;                   // 5*128*4   = 2560
static constexpr int SM_B1  = 209408;                   // 512
static constexpr int SM_B2  = 209920;                   // 512
static constexpr int EDGE_SMEM_BYTES = 210432;

__global__ void __launch_bounds__(256, 1)
edge_hmma_kernel(const float* __restrict__ edge_attr,
                 const float* __restrict__ ew1, const float* __restrict__ eb1,
                 const float* __restrict__ eb2,
                 const int* __restrict__ row, const int* __restrict__ col, int layer) {
    extern __shared__ char smem[];
    __nv_bfloat16* sAhi = (__nv_bfloat16*)(smem + SM_AHI);
    __nv_bfloat16* sAlo = (__nv_bfloat16*)(smem + SM_ALO);
    __nv_bfloat16* sBhi = (__nv_bfloat16*)(smem + SM_BHI);
    __nv_bfloat16* sBlo = (__nv_bfloat16*)(smem + SM_BLO);
    float* sD  = (float*)(smem + SM_D);
    float* sWT = (float*)(smem + SM_WT);
    float* sB1 = (float*)(smem + SM_B1);
    float* sB2 = (float*)(smem + SM_B2);

    int tid = threadIdx.x;
    int e0 = blockIdx.x * 128;

    // phase 0: stage B hi/lo (pad stride 136) + tail weights + biases
    {
        const uint4* gbh = (const uint4*)g_Bh[layer];  // 8 bf16 per uint4
        const uint4* gbl = (const uint4*)g_Bl[layer];
#pragma unroll
        for (int i = tid; i < 2048; i += 256) {
            int k = i >> 4, n8 = i & 15;
            *(uint4*)(sBhi + k * AST + n8 * 8) = gbh[i];
            *(uint4*)(sBlo + k * AST + n8 * 8) = gbl[i];
        }
        const float* Wtail = ew1 + (layer * 261 + 2 * HID) * HID;
        for (int i = tid; i < 5 * HID; i += 256) sWT[i] = Wtail[i];
        if (tid < HID) {
            sB1[tid] = eb1[layer * HID + tid];
            sB2[tid] = eb2[layer * HID + tid];
        }
    }
    __syncthreads();

    // phase 1: build A = elu(P1[row]+P2[col]+rad*w+ea@Wtail+b1) as bf16 hi/lo
    {
        int m = tid >> 1, hf = tid & 1;   // 2 threads per edge, 64 cols each
        int e = e0 + m;
        int r = row[e], c = col[e];
        float rad = g_radial[e];
        float4 ea = *(const float4*)(edge_attr + (size_t)e * 4);
        const float* p1r = g_P1 + (size_t)r * HID;
        const float* p2r = g_P2 + (size_t)c * HID;
#pragma unroll
        for (int ch = 0; ch < 2; ch++) {
#pragma unroll
            for (int q = 0; q < 8; q++) {
                int jb = hf * 64 + ch * 32 + q * 4;
                float4 p1 = *(const float4*)(p1r + jb);
                float4 p2 = *(const float4*)(p2r + jb);
                float4 w0 = *(const float4*)(sWT + 0 * HID + jb);
                float4 w1 = *(const float4*)(sWT + 1 * HID + jb);
                float4 w2 = *(const float4*)(sWT + 2 * HID + jb);
                float4 w3 = *(const float4*)(sWT + 3 * HID + jb);
                float4 w4 = *(const float4*)(sWT + 4 * HID + jb);
                float4 bb = *(const float4*)(sB1 + jb);
                float o0 = elu(p1.x + p2.x + rad * w0.x + ea.x * w1.x + ea.y * w2.x + ea.z * w3.x + ea.w * w4.x + bb.x);
                float o1 = elu(p1.y + p2.y + rad * w0.y + ea.x * w1.y + ea.y * w2.y + ea.z * w3.y + ea.w * w4.y + bb.y);
                float o2 = elu(p1.z + p2.z + rad * w0.z + ea.x * w1.z + ea.y * w2.z + ea.z * w3.z + ea.w * w4.z + bb.z);
                float o3 = elu(p1.w + p2.w + rad * w0.w + ea.x * w1.w + ea.y * w2.w + ea.z * w3.w + ea.w * w4.w + bb.w);
                float h0f = __bfloat162float(__float2bfloat16(o0));
                float h1f = __bfloat162float(__float2bfloat16(o1));
                float h2f = __bfloat162float(__float2bfloat16(o2));
                float h3f = __bfloat162float(__float2bfloat16(o3));
                uint32_t* ph = (uint32_t*)(sAhi + m * AST + jb);
                uint32_t* pl = (uint32_t*)(sAlo + m * AST + jb);
                ph[0] = pack_bf16(h0f, h1f);
                ph[1] = pack_bf16(h2f, h3f);
                pl[0] = pack_bf16(o0 - h0f, o1 - h1f);
                pl[1] = pack_bf16(o2 - h2f, o3 - h3f);
            }
        }
    }
    __syncthreads();

    // phase 2: wmma 3-pass. warp w -> M rows [m0,m0+32), N cols [n0,n0+64)
    {
        using namespace nvcuda::wmma;
        int wid = tid >> 5;
        int m0 = (wid >> 1) * 32;
        int n0 = (wid & 1) * 64;

        fragment<accumulator, 16, 16, 16, float> acc[2][4];
#pragma unroll
        for (int i = 0; i < 2; i++)
#pragma unroll
            for (int j = 0; j < 4; j++) fill_fragment(acc[i][j], 0.f);

#pragma unroll
        for (int pass = 0; pass < 3; pass++) {
            const __nv_bfloat16* Ab = (pass == 1) ? sAlo : sAhi;
            const __nv_bfloat16* Bb = (pass == 2) ? sBlo : sBhi;
#pragma unroll
            for (int k = 0; k < 8; k++) {
                fragment<matrix_a, 16, 16, 16, __nv_bfloat16, row_major> a0, a1;
                load_matrix_sync(a0, Ab + m0 * AST + k * 16, AST);
                load_matrix_sync(a1, Ab + (m0 + 16) * AST + k * 16, AST);
#pragma unroll
                for (int nt = 0; nt < 4; nt++) {
                    fragment<matrix_b, 16, 16, 16, __nv_bfloat16, row_major> b;
                    load_matrix_sync(b, Bb + (k * 16) * AST + n0 + nt * 16, AST);
                    mma_sync(acc[0][nt], a0, b, acc[0][nt]);
                    mma_sync(acc[1][nt], a1, b, acc[1][nt]);
                }
            }
        }
#pragma unroll
        for (int i = 0; i < 2; i++)
#pragma unroll
            for (int nt = 0; nt < 4; nt++)
                store_matrix_sync(sD + (m0 + i * 16) * DST + n0 + nt * 16,
                                  acc[i][nt], DST, mem_row_major);
    }
    __syncthreads();

    // phase 3: elu + bias, scatter-add to g_agg
    {
        int m = tid & 127, hf = tid >> 7;
        int e = e0 + m;
        int r = row[e];
        const float* sd = sD + m * DST + hf * 64;
        const float* sb2 = sB2 + hf * 64;
        float* dst = g_agg + (size_t)r * HID + hf * 64;
#pragma unroll
        for (int j = 0; j < 64; j += 4) {
            float v0 = elu(sd[j + 0] + sb2[j + 0]);
            float v1 = elu(sd[j + 1] + sb2[j + 1]);
            float v2 = elu(sd[j + 2] + sb2[j + 2]);
            float v3 = elu(sd[j + 3] + sb2[j + 3]);
            red4(dst + j, v0, v1, v2, v3);
        }
    }
}

// ---------------- node kernel (fp32 SIMT) ----------------
__global__ void __launch_bounds__(256, 2)
node_kernel(const float* __restrict__ nw1, const float* __restrict__ nb1,
            const float* __restrict__ nw2, const float* __restrict__ nb2, int layer) {
    extern __shared__ float sm[];
    float* Ts = sm;
    float* As = sm + 128 * 132;
    float* Bs = As + 32 * 132;

    const float* hsrc = (layer == 0) ? g_h0buf : g_h1buf;
    float* hdst = (layer == 0) ? g_h1buf : g_h0buf;

    int tid = threadIdx.x;
    int tx = tid & 15, ty = tid >> 4;
    int n0 = blockIdx.x * 128;

    float acc[8][8];
#pragma unroll
    for (int i = 0; i < 8; i++)
#pragma unroll
        for (int j = 0; j < 8; j++) acc[i][j] = 0.f;

    for (int k0 = 0; k0 < 2 * HID; k0 += 32) {
        const float* Asrc = (k0 < HID) ? (hsrc + k0) : (g_agg + (k0 - HID));
        const float* Bsrc = (k0 < HID) ? (g_wsum + k0 * HID)
                                       : (nw1 + (layer * 3 * HID + HID + (k0 - HID)) * HID);
#pragma unroll
        for (int it = 0; it < 4; it++) {
            int s = tid + it * 256;
            int e = s >> 3, kq = s & 7;
            int n = n0 + e;
            float4 v = make_float4(0.f, 0.f, 0.f, 0.f);
            if (n < NN) v = *(const float4*)(Asrc + n * HID + kq * 4);
            As[(kq * 4 + 0) * 132 + e] = v.x;
            As[(kq * 4 + 1) * 132 + e] = v.y;
            As[(kq * 4 + 2) * 132 + e] = v.z;
            As[(kq * 4 + 3) * 132 + e] = v.w;
        }
#pragma unroll
        for (int it = 0; it < 4; it++) {
            int s = tid + it * 256;
            int kk = s >> 5, jq = s & 31;
            *(float4*)(Bs + kk * 132 + jq * 4) =
                *(const float4*)(Bsrc + kk * HID + jq * 4);
        }
        __syncthreads();
#pragma unroll
        for (int kk = 0; kk < 32; kk++) {
            float4 a0 = *(const float4*)(As + kk * 132 + ty * 8);
            float4 a1 = *(const float4*)(As + kk * 132 + ty * 8 + 4);
            float4 b0 = *(const float4*)(Bs + kk * 132 + tx * 8);
            float4 b4 = *(const float4*)(Bs + kk * 132 + tx * 8 + 4);
            float a[8] = {a0.x, a0.y, a0.z, a0.w, a1.x, a1.y, a1.z, a1.w};
            float b[8] = {b0.x, b0.y, b0.z, b0.w, b4.x, b4.y, b4.z, b4.w};
#pragma unroll
            for (int i = 0; i < 8; i++)
#pragma unroll
                for (int j = 0; j < 8; j++) acc[i][j] += a[i] * b[j];
        }
        __syncthreads();
    }

    const float* b1 = nb1 + layer * HID;
#pragma unroll
    for (int i = 0; i < 8; i++)
#pragma unroll
        for (int j = 0; j < 8; j++)
            Ts[(ty * 8 + i) * 132 + tx * 8 + j] = elu(acc[i][j] + b1[tx * 8 + j]);

#pragma unroll
    for (int i = 0; i < 8; i++)
#pragma unroll
        for (int j = 0; j < 8; j++) acc[i][j] = 0.f;

    const float* W2 = nw2 + layer * HID * HID;
    for (int k0 = 0; k0 < HID; k0 += 32) {
#pragma unroll
        for (int it = 0; it < 4; it++) {
            int s = tid + it * 256;
            int kk = s >> 5, jq = s & 31;
            *(float4*)(Bs + kk * 132 + jq * 4) =
                *(const float4*)(W2 + (k0 + kk) * HID + jq * 4);
        }
        __syncthreads();
#pragma unroll
        for (int kk = 0; kk < 32; kk++) {
            float a[8];
#pragma unroll
            for (int i = 0; i < 8; i++) a[i] = Ts[(ty * 8 + i) * 132 + k0 + kk];
            float4 b0 = *(const float4*)(Bs + kk * 132 + tx * 8);
            float4 b4 = *(const float4*)(Bs + kk * 132 + tx * 8 + 4);
            float b[8] = {b0.x, b0.y, b0.z, b0.w, b4.x, b4.y, b4.z, b4.w};
#pragma unroll
            for (int i = 0; i < 8; i++)
#pragma unroll
                for (int j = 0; j < 8; j++) acc[i][j] += a[i] * b[j];
        }
        __syncthreads();
    }

    const float* b2 = nb2 + layer * HID;
#pragma unroll
    for (int i = 0; i < 8; i++) {
        int n = n0 + ty * 8 + i;
        if (n < NN) {
#pragma unroll
            for (int j = 0; j < 8; j++)
                hdst[n * HID + tx * 8 + j] = acc[i][j] + b2[tx * 8 + j];
        }
    }
}

// ---------------- final head ----------------
__global__ void final_kernel(const float* __restrict__ label,
                             const float* __restrict__ eps,
                             const float* __restrict__ mu_w, const float* __restrict__ mu_b,
                             const float* __restrict__ var_w, const float* __restrict__ var_b,
                             float* __restrict__ out) {
    int idx = blockIdx.x * 256 + threadIdx.x;
    if (idx >= NN * LATD) return;
    int n = idx >> 6, l = idx & 63;
    float am = mu_b[l], av = var_b[l];
    const float* hrow = g_h0buf + n * HID;
#pragma unroll 4
    for (int k = 0; k < HID; k++) {
        float hv = hrow[k];
        am += hv * mu_w[k * LATD + l];
        av += hv * var_w[k * LATD + l];
    }
#pragma unroll
    for (int c = 0; c < 7; c++) {
        float lv = label[n * 7 + c];
        am += lv * mu_w[(HID + c) * LATD + l];
        av += lv * var_w[(HID + c) * LATD + l];
    }
    out[idx] = am + 0.01f * eps[idx] * __expf(0.5f * av);
}

// ---------------- launch ----------------
extern "C" void kernel_launch(void* const* d_in, const int* in_sizes, int n_in,
                              void* d_out, int out_size) {
    const float* h0        = (const float*)d_in[0];
    const float* label     = (const float*)d_in[1];
    const float* x         = (const float*)d_in[2];
    const float* edge_attr = (const float*)d_in[3];
    const float* eps       = (const float*)d_in[4];
    const float* emb_w     = (const float*)d_in[5];
    const float* emb_b     = (const float*)d_in[6];
    const float* ew1       = (const float*)d_in[7];
    const float* eb1       = (const float*)d_in[8];
    const float* ew2       = (const float*)d_in[9];
    const float* eb2       = (const float*)d_in[10];
    const float* nw1       = (const float*)d_in[11];
    const float* nb1       = (const float*)d_in[12];
    const float* nw2       = (const float*)d_in[13];
    const float* nb2       = (const float*)d_in[14];
    const float* mu_w      = (const float*)d_in[15];
    const float* mu_b      = (const float*)d_in[16];
    const float* var_w     = (const float*)d_in[17];
    const float* var_b     = (const float*)d_in[18];
    const int*   edges     = (const int*)d_in[19];
    const int* rowp = edges;
    const int* colp = edges + NE;
    float* out = (float*)d_out;

    const int NODE_SMEM = (128 * 132 + 32 * 132 + 32 * 132) * 4;
    cudaFuncSetAttribute(edge_hmma_kernel, cudaFuncAttributeMaxDynamicSharedMemorySize, EDGE_SMEM_BYTES);
    cudaFuncSetAttribute(node_kernel, cudaFuncAttributeMaxDynamicSharedMemorySize, NODE_SMEM);

    embed_kernel<<<(NN * HID + 255) / 256, 256>>>(h0, emb_w, emb_b);
    radial_kernel<<<(NE + 255) / 256, 256>>>(x, rowp, colp);
    w2prep_kernel<<<(2 * HID * HID + 255) / 256, 256>>>(ew2);

    for (int layer = 0; layer < 2; layer++) {
        zero_agg_kernel<<<(NN * HID + 255) / 256, 256>>>();
        pre_kernel<<<dim3((NN + 127) / 128, 2), 256>>>(ew1, layer);
        wsum_kernel<<<(HID * HID + 255) / 256, 256>>>(nw1, layer);
        edge_hmma_kernel<<<NE / 128, 256, EDGE_SMEM_BYTES>>>(edge_attr, ew1, eb1, eb2,
                                                             rowp, colp, layer);
        node_kernel<<<(NN + 127) / 128, 256, NODE_SMEM>>>(nw1, nb1, nw2, nb2, layer);
    }

    final_kernel<<<(NN * LATD + 255) / 256, 256>>>(label, eps, mu_w, mu_b,
                                                   var_w, var_b, out);
}